// round 9
// baseline (speedup 1.0000x reference)
#include <cuda_runtime.h>
#include <cuda_fp16.h>

#define N_LAYERS 30
#define T_LEN    262144
#define BATCH    8
#define NTH      128
#define NPAIR    12
#define LEXT     3072                    // NTH*2*NPAIR
#define HALO     576
#define TILE     (LEXT - HALO)           // 2496
#define NTILES   106                     // 106*2496 = 264576 >= 262144
#define NCTAS    (NTILES * BATCH)        // 848 <= 148*6 = 888 slots
#define PADL     32
#define PADW     (PADL/2)                // 16 words
#define BUFU32   (PADW + LEXT/2)         // 1552 words per f16x2 buffer
#define WOFFB    (2 * BUFU32 * 4)        // 12416
#define SMEM_BYTES (WOFFB + 448 * 4)     // 14208

#define LN256  5.545177444479562f
#define NEGBIG -3.402823466e38f

typedef unsigned long long u64;
typedef unsigned int u32;

__device__ float g_tilemax[NCTAS];
__device__ float g_tilesum[NCTAS];
__device__ u32   g_arrive;   // zero-init
__device__ u32   g_epoch;    // zero-init

// ---------- f16x2 helpers ----------
__device__ __forceinline__ u32 hfma2(u32 a, u32 b, u32 c) {
    u32 d; asm("fma.rn.f16x2 %0,%1,%2,%3;" : "=r"(d) : "r"(a), "r"(b), "r"(c)); return d;
}
__device__ __forceinline__ u32 hmul2(u32 a, u32 b) {
    u32 d; asm("mul.rn.f16x2 %0,%1,%2;" : "=r"(d) : "r"(a), "r"(b)); return d;
}
__device__ __forceinline__ u32 hadd2(u32 a, u32 b) {
    u32 d; asm("add.rn.f16x2 %0,%1,%2;" : "=r"(d) : "r"(a), "r"(b)); return d;
}
__device__ __forceinline__ u32 htanh2(u32 a) {
    u32 d; asm("tanh.approx.f16x2 %0,%1;" : "=r"(d) : "r"(a)); return d;
}
__device__ __forceinline__ u32 pkh(float lo, float hi) {
    u32 d; asm("cvt.rn.f16x2.f32 %0,%1,%2;" : "=r"(d) : "f"(hi), "f"(lo)); return d;
}
__device__ __forceinline__ u32 duph(float w) {
    u32 d; asm("cvt.rn.f16x2.f32 %0,%1,%1;" : "=r"(d) : "f"(w)); return d;
}
__device__ __forceinline__ float2 uph(u32 v) {
    __half2 h = *reinterpret_cast<__half2*>(&v);
    return __half22float2(h);
}
__device__ __forceinline__ u32 prmt5432(u32 a, u32 b) {
    u32 d; asm("prmt.b32 %0,%1,%2,0x5432;" : "=r"(d) : "r"(a), "r"(b)); return d;
}

// One gated residual layer, even dilation D, f16x2, bias-folded residual.
template<int D, bool STORE>
__device__ __forceinline__ void layer_even(int k, const u32* cur, u32* nxt,
                                           const float* ws, int tid, bool zh,
                                           u32* hreg, u32* sreg, u32 halfh)
{
    const u32 fw0 = duph(ws[8+5*k]),  fw1 = duph(ws[9+5*k]),  fw2 = duph(ws[10+5*k]);
    const u32 fw3 = duph(ws[11+5*k]), fw4 = duph(ws[12+5*k]);
    const u32 gw0 = duph(ws[188+5*k]), gw1 = duph(ws[189+5*k]), gw2 = duph(ws[190+5*k]);
    const u32 gw3 = duph(ws[191+5*k]), gw4 = duph(ws[192+5*k]);
    const u32 fb2 = duph(ws[158+k]), gb2 = duph(ws[338+k]);
    u32 rw2 = 0, negc = 0;
    if (STORE) { rw2 = duph(ws[368+k]); negc = duph(ws[398+k]); }

    #pragma unroll
    for (int p = 0; p < NPAIR; p++) {
        int q = tid + p * NTH;
        const u32* s = cur + PADW + q;
        u32 t1 = s[-(D/2)];
        u32 t2 = s[-D];
        u32 t3 = s[-(3*D/2)];
        u32 t4 = s[-2*D];
        u32 t0 = hreg[p];

        u32 fp = hfma2(fw4, t0, hfma2(fw3, t1, hfma2(fw2, t2, hfma2(fw1, t3, hfma2(fw0, t4, fb2)))));
        u32 gp = hfma2(gw4, t0, hfma2(gw3, t1, hfma2(gw2, t2, hfma2(gw1, t3, hfma2(gw0, t4, gb2)))));

        u32 f2v = htanh2(fp);
        u32 g2v = hfma2(htanh2(gp), halfh, halfh);   // sigmoid (gate pre-scaled 0.5)
        u32 z   = hmul2(f2v, g2v);
        sreg[p] = hadd2(sreg[p], z);
        if (STORE) {
            u32 hn = hfma2(z, rw2, t0);              // rb folded into next biases
            if (zh && 2*q < HALO) hn = negc;         // H = -C_{k+1} in zero-pad halo
            hreg[p] = hn;
            nxt[PADW + q] = hn;
        }
    }
    if (STORE) __syncthreads();
}

__global__ __launch_bounds__(NTH, 6)
void wavenet_k1(const float* __restrict__ x,
                const float* __restrict__ cw,  const float* __restrict__ cb,
                const float* __restrict__ fw,  const float* __restrict__ fb,
                const float* __restrict__ gw,  const float* __restrict__ gb,
                const float* __restrict__ rw,  const float* __restrict__ rb,
                const float* __restrict__ c1w, const float* __restrict__ c1b,
                const float* __restrict__ c2w, const float* __restrict__ c2b,
                float* __restrict__ out)
{
    extern __shared__ char smem[];
    u32*   b0 = (u32*)smem;
    u32*   b1 = b0 + BUFU32;
    float* ws = (float*)(smem + WOFFB);

    const int tid  = threadIdx.x;
    const int tile = blockIdx.x;
    const int b    = blockIdx.y;
    const long long base = (long long)b * T_LEN;
    const int g0 = tile * TILE - HALO;
    const bool zh = (tile == 0);

    // ---- weights -> smem (gate pre-scaled by 0.5) ----
    if (tid < 5)  ws[tid] = cw[tid];
    if (tid == 5) ws[5]   = cb[0];
    for (int j = tid; j < 150; j += NTH) { ws[8 + j] = fw[j]; ws[188 + j] = gw[j] * 0.5f; }
    for (int j = tid; j < 30;  j += NTH) {
        ws[158 + j] = fb[j]; ws[338 + j] = gb[j] * 0.5f;
        ws[368 + j] = rw[j]; ws[398 + j] = rb[j];
    }
    if (tid == 0) { ws[428] = c1w[0]; ws[429] = c1b[0]; ws[430] = c2w[0]; ws[431] = c2b[0]; }
    if (tid < PADW) { b0[tid] = 0u; b1[tid] = 0u; }
    __syncthreads();

    // ---- thread 0: fold cumulative residual bias C into conv biases ----
    // H_k = h_k - C_k, C_{k+1} = C_k + rb_k; taps share C -> fb' = fb + C*sum(fw)
    if (tid == 0) {
        float C = 0.0f;
        for (int k = 0; k < N_LAYERS; k++) {
            float sf = ws[8+5*k] + ws[9+5*k] + ws[10+5*k] + ws[11+5*k] + ws[12+5*k];
            float sg = ws[188+5*k] + ws[189+5*k] + ws[190+5*k] + ws[191+5*k] + ws[192+5*k];
            ws[158+k] += C * sf;
            ws[338+k] += C * sg;     // gate side already carries the 0.5 scale
            C += ws[398+k];          // raw rb_k
            ws[398+k] = -C;          // -C_{k+1} (halo forcing constant)
        }
    }

    // ---- stage x -> f16x2 buf0 ----
    #pragma unroll
    for (int p = 0; p < NPAIR; p++) {
        int q = tid + p * NTH;
        int g = g0 + 2*q;
        float2 v;
        if (g >= 0 && g + 1 < T_LEN) {
            v = *(const float2*)(x + base + g);
        } else {
            v.x = (g     >= 0 && g     < T_LEN) ? x[base + g]     : 0.0f;
            v.y = (g + 1 >= 0 && g + 1 < T_LEN) ? x[base + g + 1] : 0.0f;
        }
        b0[PADW + q] = pkh(v.x, v.y);
    }
    __syncthreads();   // also covers thread 0's bias fold

    const u32 halfh = duph(0.5f);
    u32 hreg[NPAIR];
    u32 sreg[NPAIR];

    // ---- causal conv (d=1): b0 -> b1 + hreg (C_0 = 0) ----
    {
        const u32 w02 = duph(ws[0]), w12 = duph(ws[1]), w22 = duph(ws[2]),
                  w32 = duph(ws[3]), w42 = duph(ws[4]), bc2 = duph(ws[5]);
        #pragma unroll
        for (int p = 0; p < NPAIR; p++) {
            int q = tid + p * NTH;
            const u32* s = b0 + PADW + q;
            u32 t0  = s[0];
            u32 wm1 = s[-1];
            u32 wm2 = s[-2];
            u32 t1 = prmt5432(wm1, t0);
            u32 t2 = wm1;
            u32 t3 = prmt5432(wm2, wm1);
            u32 t4 = wm2;
            u32 v = hfma2(w42, t0, hfma2(w32, t1, hfma2(w22, t2, hfma2(w12, t3, hfma2(w02, t4, bc2)))));
            if (zh && 2*q < HALO) v = 0u;
            hreg[p] = v;
            sreg[p] = 0u;
            b1[PADW + q] = v;
        }
    }
    __syncthreads();

    u32* cur = b1;
    u32* nxt = b0;

    // ---- layer 0 (d=1): odd offsets via PRMT ----
    {
        const u32 fw0 = duph(ws[8]),   fw1 = duph(ws[9]),   fw2 = duph(ws[10]);
        const u32 fw3 = duph(ws[11]),  fw4 = duph(ws[12]);
        const u32 gw0 = duph(ws[188]), gw1 = duph(ws[189]), gw2 = duph(ws[190]);
        const u32 gw3 = duph(ws[191]), gw4 = duph(ws[192]);
        const u32 fb2 = duph(ws[158]), gb2 = duph(ws[338]);
        const u32 rw2 = duph(ws[368]), negc = duph(ws[398]);
        #pragma unroll
        for (int p = 0; p < NPAIR; p++) {
            int q = tid + p * NTH;
            const u32* s = cur + PADW + q;
            u32 t0  = hreg[p];
            u32 wm1 = s[-1];
            u32 wm2 = s[-2];
            u32 t1 = prmt5432(wm1, t0);
            u32 t2 = wm1;
            u32 t3 = prmt5432(wm2, wm1);
            u32 t4 = wm2;

            u32 fp = hfma2(fw4, t0, hfma2(fw3, t1, hfma2(fw2, t2, hfma2(fw1, t3, hfma2(fw0, t4, fb2)))));
            u32 gp = hfma2(gw4, t0, hfma2(gw3, t1, hfma2(gw2, t2, hfma2(gw1, t3, hfma2(gw0, t4, gb2)))));

            u32 f2v = htanh2(fp);
            u32 g2v = hfma2(htanh2(gp), halfh, halfh);
            u32 z   = hmul2(f2v, g2v);
            sreg[p] = hadd2(sreg[p], z);
            u32 hn  = hfma2(z, rw2, t0);
            if (zh && 2*q < HALO) hn = negc;
            hreg[p] = hn;
            nxt[PADW + q] = hn;
        }
        __syncthreads();
        u32* tmp = cur; cur = nxt; nxt = tmp;
    }

    // ---- layers 1..28: static dilation cycle (2,4,8,6) x 7 ----
    int k = 1;
    #pragma unroll 1
    for (int j = 0; j < 7; j++) {
        layer_even<2, true>(k,   cur, nxt, ws, tid, zh, hreg, sreg, halfh);
        { u32* t = cur; cur = nxt; nxt = t; }
        layer_even<4, true>(k+1, cur, nxt, ws, tid, zh, hreg, sreg, halfh);
        { u32* t = cur; cur = nxt; nxt = t; }
        layer_even<8, true>(k+2, cur, nxt, ws, tid, zh, hreg, sreg, halfh);
        { u32* t = cur; cur = nxt; nxt = t; }
        layer_even<6, true>(k+3, cur, nxt, ws, tid, zh, hreg, sreg, halfh);
        { u32* t = cur; cur = nxt; nxt = t; }
        k += 4;
    }
    // ---- layer 29 (d=2): skips only ----
    layer_even<2, false>(29, cur, nxt, ws, tid, zh, hreg, sreg, halfh);

    // ---- epilogue: 1x1 convs + mu-law; park v as f32 in smem ----
    const float c1wv = ws[428], c1bv = ws[429], c2wv = ws[430], c2bv = ws[431];
    __syncthreads();                       // layer-29 reads of cur complete
    float2* vbuf = (float2*)smem;          // LEXT/2=1536 float2 = 12288 B <= 12416 B
    float*  red  = (float*)(smem + WOFFB); // 128 floats; clobbers dead weights
    float lmax = NEGBIG;
    #pragma unroll
    for (int p = 0; p < NPAIR; p++) {
        int q = tid + p * NTH;
        int i = 2*q;
        int g = g0 + i;
        float v0 = NEGBIG, v1 = NEGBIG;
        if (i >= HALO && g < T_LEN) {      // g even, T_LEN even -> g+1 also valid
            float2 sv = uph(sreg[p]);
            float r0 = fmaf(fmaxf(sv.x, 0.0f), c1wv, c1bv);
            r0 = fmaf(fmaxf(r0, 0.0f), c2wv, c2bv);
            v0 = copysignf((__expf(fabsf(r0) * LN256) - 1.0f) * (1.0f / 255.0f), r0);
            float r1 = fmaf(fmaxf(sv.y, 0.0f), c1wv, c1bv);
            r1 = fmaf(fmaxf(r1, 0.0f), c2wv, c2bv);
            v1 = copysignf((__expf(fabsf(r1) * LN256) - 1.0f) * (1.0f / 255.0f), r1);
        }
        vbuf[q] = make_float2(v0, v1);
        lmax = fmaxf(lmax, fmaxf(v0, v1));
    }
    __syncthreads();

    // ---- tile max ----
    red[tid] = lmax;
    __syncthreads();
    #pragma unroll
    for (int off = 64; off > 0; off >>= 1) {
        if (tid < off) red[tid] = fmaxf(red[tid], red[tid + off]);
        __syncthreads();
    }
    const float tmax = red[0];
    __syncthreads();

    // ---- tile exp-sum (v from smem) ----
    float lsum = 0.0f;
    #pragma unroll
    for (int p = 0; p < NPAIR; p++) {
        int q = tid + p * NTH;
        float2 v = vbuf[q];
        lsum += __expf(v.x - tmax) + __expf(v.y - tmax);
    }
    red[tid] = lsum;
    __syncthreads();
    #pragma unroll
    for (int off = 64; off > 0; off >>= 1) {
        if (tid < off) red[tid] = red[tid] + red[tid + off];
        __syncthreads();
    }
    if (tid == 0) {
        g_tilemax[b * NTILES + tile] = tmax;
        g_tilesum[b * NTILES + tile] = red[0];
        __threadfence();
    }
    __syncthreads();

    // ---- software grid barrier (848 CTAs co-resident in 888 slots) ----
    if (tid == 0) {
        volatile u32* ep = &g_epoch;
        u32 my = *ep;
        u32 t = atomicAdd(&g_arrive, 1u);
        if (t == NCTAS - 1) {
            g_arrive = 0;
            __threadfence();
            atomicAdd(&g_epoch, 1u);
        } else {
            long long guard = 0;
            while (*ep == my && guard < (1LL << 30)) { __nanosleep(64); guard++; }
        }
        __threadfence();
    }
    __syncthreads();

    // ---- combine all tiles of this batch -> bmax, inv; final write ----
    {
        volatile float* vtm = (volatile float*)g_tilemax;
        volatile float* vts = (volatile float*)g_tilesum;
        float m = NEGBIG, s = 0.0f;
        if (tid < NTILES) { m = vtm[b * NTILES + tid]; s = vts[b * NTILES + tid]; }
        red[tid] = m;
        __syncthreads();
        #pragma unroll
        for (int off = 64; off > 0; off >>= 1) {
            if (tid < off) red[tid] = fmaxf(red[tid], red[tid + off]);
            __syncthreads();
        }
        float bmax = red[0];
        __syncthreads();
        red[tid] = (tid < NTILES) ? s * __expf(m - bmax) : 0.0f;
        __syncthreads();
        #pragma unroll
        for (int off = 64; off > 0; off >>= 1) {
            if (tid < off) red[tid] = red[tid] + red[tid + off];
            __syncthreads();
        }
        float inv = 1.0f / red[0];

        #pragma unroll
        for (int p = 0; p < NPAIR; p++) {
            int q = tid + p * NTH;
            int i = 2*q;
            int g = g0 + i;
            if (i >= HALO && g < T_LEN) {
                float2 v = vbuf[q];
                float e0 = __expf(v.x - bmax) * inv;
                float e1 = __expf(v.y - bmax) * inv;
                *(float2*)(out + base + g) = make_float2(e0, e1);
            }
        }
    }
}

extern "C" void kernel_launch(void* const* d_in, const int* in_sizes, int n_in,
                              void* d_out, int out_size)
{
    const float* x   = (const float*)d_in[0];
    const float* cw  = (const float*)d_in[1];
    const float* cb  = (const float*)d_in[2];
    const float* fw  = (const float*)d_in[3];
    const float* fb  = (const float*)d_in[4];
    const float* gw  = (const float*)d_in[5];
    const float* gb  = (const float*)d_in[6];
    const float* rw  = (const float*)d_in[7];
    const float* rb  = (const float*)d_in[8];
    const float* c1w = (const float*)d_in[9];
    const float* c1b = (const float*)d_in[10];
    const float* c2w = (const float*)d_in[11];
    const float* c2b = (const float*)d_in[12];
    float* out = (float*)d_out;

    cudaFuncSetAttribute(wavenet_k1, cudaFuncAttributeMaxDynamicSharedMemorySize, SMEM_BYTES);

    wavenet_k1<<<dim3(NTILES, BATCH), NTH, SMEM_BYTES>>>(
        x, cw, cb, fw, fb, gw, gb, rw, rb, c1w, c1b, c2w, c2b, out);
}

// round 10
// speedup vs baseline: 1.0685x; 1.0685x over previous
#include <cuda_runtime.h>
#include <cuda_fp16.h>

#define N_LAYERS 30
#define T_LEN    262144
#define BATCH    8
#define NTH      384
#define NWARP    12
#define NPAIR    10
#define WREG     (32 * NPAIR)            // 320 words per warp (contiguous)
#define LEXT     7680                    // NTH*2*NPAIR samples
#define HALO     576
#define TILE     (LEXT - HALO)           // 7104
#define NTILES   37
#define NCTAS    (NTILES * BATCH)        // 296 = 148 SMs x occ 2
#define PADL     32
#define PADW     (PADL/2)                // 16 words
#define BUFU32   (PADW + LEXT/2)         // 3856 words per f16x2 buffer
#define WOFFB    (2 * BUFU32 * 4)        // 30848
#define SMEM_BYTES (WOFFB + 448 * 4)     // 32640

#define LN256  5.545177444479562f
#define NEGBIG -3.402823466e38f

typedef unsigned long long u64;
typedef unsigned int u32;

__device__ float g_tilemax[NCTAS];
__device__ float g_tilesum[NCTAS];
__device__ u32   g_arrive;   // zero-init
__device__ u32   g_epoch;    // zero-init

// ---------- f32x2 helpers (epilogue only) ----------
__device__ __forceinline__ u64 pk(float lo, float hi) {
    u64 r; asm("mov.b64 %0,{%1,%2};" : "=l"(r) : "f"(lo), "f"(hi)); return r;
}
__device__ __forceinline__ void upk(u64 v, float& lo, float& hi) {
    asm("mov.b64 {%0,%1},%2;" : "=f"(lo), "=f"(hi) : "l"(v));
}

// ---------- f16x2 helpers ----------
__device__ __forceinline__ u32 hfma2(u32 a, u32 b, u32 c) {
    u32 d; asm("fma.rn.f16x2 %0,%1,%2,%3;" : "=r"(d) : "r"(a), "r"(b), "r"(c)); return d;
}
__device__ __forceinline__ u32 hmul2(u32 a, u32 b) {
    u32 d; asm("mul.rn.f16x2 %0,%1,%2;" : "=r"(d) : "r"(a), "r"(b)); return d;
}
__device__ __forceinline__ u32 hadd2(u32 a, u32 b) {
    u32 d; asm("add.rn.f16x2 %0,%1,%2;" : "=r"(d) : "r"(a), "r"(b)); return d;
}
__device__ __forceinline__ u32 htanh2(u32 a) {
    u32 d; asm("tanh.approx.f16x2 %0,%1;" : "=r"(d) : "r"(a)); return d;
}
__device__ __forceinline__ u32 pkh(float lo, float hi) {
    u32 d; asm("cvt.rn.f16x2.f32 %0,%1,%2;" : "=r"(d) : "f"(hi), "f"(lo)); return d;
}
__device__ __forceinline__ u32 duph(float w) {
    u32 d; asm("cvt.rn.f16x2.f32 %0,%1,%1;" : "=r"(d) : "f"(w)); return d;
}
__device__ __forceinline__ float2 uph(u32 v) {
    __half2 h = *reinterpret_cast<__half2*>(&v);
    return __half22float2(h);
}
__device__ __forceinline__ u32 prmt5432(u32 a, u32 b) {
    u32 d; asm("prmt.b32 %0,%1,%2,0x5432;" : "=r"(d) : "r"(a), "r"(b)); return d;
}
// Named barrier: rendezvous of exactly 2 warps (64 threads)
__device__ __forceinline__ void barw(int id) {
    asm volatile("bar.sync %0, 64;" :: "r"(id) : "memory");
}
// Neighbor sync: left rendezvous (id=wid), then right (id=wid+1).
// Causal taps -> warp w reads only warp w-1's region; double-buffered smem
// makes the one-layer neighbor skew safe in both RAW and WAR directions.
__device__ __forceinline__ void nbr_sync(int wid) {
    if (wid > 0)         barw(wid);
    if (wid < NWARP - 1) barw(wid + 1);
}

// One gated residual layer, even dilation D, f16x2, bias-folded residual.
// Contiguous per-warp ownership: q = wid*WREG + lane + 32*p.
template<int D, bool STORE>
__device__ __forceinline__ void layer_even(int k, const u32* cur, u32* nxt,
                                           const float* ws, int bq, int wid, bool zh,
                                           u32* hreg, u32* sreg, u32 halfh)
{
    const u32 fw0 = duph(ws[8+5*k]),  fw1 = duph(ws[9+5*k]),  fw2 = duph(ws[10+5*k]);
    const u32 fw3 = duph(ws[11+5*k]), fw4 = duph(ws[12+5*k]);
    const u32 gw0 = duph(ws[188+5*k]), gw1 = duph(ws[189+5*k]), gw2 = duph(ws[190+5*k]);
    const u32 gw3 = duph(ws[191+5*k]), gw4 = duph(ws[192+5*k]);
    const u32 fb2 = duph(ws[158+k]), gb2 = duph(ws[338+k]);
    u32 rw2 = 0, negc = 0;
    if (STORE) { rw2 = duph(ws[368+k]); negc = duph(ws[398+k]); }

    #pragma unroll
    for (int p = 0; p < NPAIR; p++) {
        int q = bq + 32 * p;
        const u32* s = cur + PADW + q;
        u32 t1 = s[-(D/2)];
        u32 t2 = s[-D];
        u32 t3 = s[-(3*D/2)];
        u32 t4 = s[-2*D];
        u32 t0 = hreg[p];

        u32 fp = hfma2(fw4, t0, hfma2(fw3, t1, hfma2(fw2, t2, hfma2(fw1, t3, hfma2(fw0, t4, fb2)))));
        u32 gp = hfma2(gw4, t0, hfma2(gw3, t1, hfma2(gw2, t2, hfma2(gw1, t3, hfma2(gw0, t4, gb2)))));

        u32 f2v = htanh2(fp);
        u32 g2v = hfma2(htanh2(gp), halfh, halfh);   // sigmoid (gate pre-scaled 0.5)
        u32 z   = hmul2(f2v, g2v);
        sreg[p] = hadd2(sreg[p], z);
        if (STORE) {
            u32 hn = hfma2(z, rw2, t0);              // rb folded into next biases
            if (zh && 2*q < HALO) hn = negc;         // H = -C_{k+1} in zero-pad halo
            hreg[p] = hn;
            nxt[PADW + q] = hn;
        }
    }
    if (STORE) nbr_sync(wid);
}

__global__ __launch_bounds__(NTH, 2)
void wavenet_k1(const float* __restrict__ x,
                const float* __restrict__ cw,  const float* __restrict__ cb,
                const float* __restrict__ fw,  const float* __restrict__ fb,
                const float* __restrict__ gw,  const float* __restrict__ gb,
                const float* __restrict__ rw,  const float* __restrict__ rb,
                const float* __restrict__ c1w, const float* __restrict__ c1b,
                const float* __restrict__ c2w, const float* __restrict__ c2b,
                float* __restrict__ out)
{
    extern __shared__ char smem[];
    u32*   b0 = (u32*)smem;
    u32*   b1 = b0 + BUFU32;
    float* ws = (float*)(smem + WOFFB);

    const int tid  = threadIdx.x;
    const int wid  = tid >> 5;
    const int lane = tid & 31;
    const int bq   = wid * WREG + lane;   // contiguous per-warp span
    const int tile = blockIdx.x;
    const int b    = blockIdx.y;
    const long long base = (long long)b * T_LEN;
    const int g0 = tile * TILE - HALO;
    const bool zh = (tile == 0);

    // ---- weights -> smem (gate pre-scaled by 0.5) ----
    if (tid < 5)  ws[tid] = cw[tid];
    if (tid == 5) ws[5]   = cb[0];
    for (int j = tid; j < 150; j += NTH) { ws[8 + j] = fw[j]; ws[188 + j] = gw[j] * 0.5f; }
    for (int j = tid; j < 30;  j += NTH) {
        ws[158 + j] = fb[j]; ws[338 + j] = gb[j] * 0.5f;
        ws[368 + j] = rw[j]; ws[398 + j] = rb[j];
    }
    if (tid == 0) { ws[428] = c1w[0]; ws[429] = c1b[0]; ws[430] = c2w[0]; ws[431] = c2b[0]; }
    if (tid < PADW) { b0[tid] = 0u; b1[tid] = 0u; }
    __syncthreads();

    // ---- thread 0: fold cumulative residual bias C into conv biases ----
    if (tid == 0) {
        float C = 0.0f;
        for (int k = 0; k < N_LAYERS; k++) {
            float sf = ws[8+5*k] + ws[9+5*k] + ws[10+5*k] + ws[11+5*k] + ws[12+5*k];
            float sg = ws[188+5*k] + ws[189+5*k] + ws[190+5*k] + ws[191+5*k] + ws[192+5*k];
            ws[158+k] += C * sf;
            ws[338+k] += C * sg;
            C += ws[398+k];
            ws[398+k] = -C;
        }
    }

    // ---- stage x -> f16x2 buf0 ----
    #pragma unroll
    for (int p = 0; p < NPAIR; p++) {
        int q = bq + 32 * p;
        int g = g0 + 2*q;
        float2 v;
        if (g >= 0 && g + 1 < T_LEN) {
            v = *(const float2*)(x + base + g);
        } else {
            v.x = (g     >= 0 && g     < T_LEN) ? x[base + g]     : 0.0f;
            v.y = (g + 1 >= 0 && g + 1 < T_LEN) ? x[base + g + 1] : 0.0f;
        }
        b0[PADW + q] = pkh(v.x, v.y);
    }
    __syncthreads();   // covers staging + bias fold (full sync: ws read by all)

    const u32 halfh = duph(0.5f);
    u32 hreg[NPAIR];
    u32 sreg[NPAIR];

    // ---- causal conv (d=1): b0 -> b1 + hreg (C_0 = 0) ----
    {
        const u32 w02 = duph(ws[0]), w12 = duph(ws[1]), w22 = duph(ws[2]),
                  w32 = duph(ws[3]), w42 = duph(ws[4]), bc2 = duph(ws[5]);
        #pragma unroll
        for (int p = 0; p < NPAIR; p++) {
            int q = bq + 32 * p;
            const u32* s = b0 + PADW + q;
            u32 t0  = s[0];
            u32 wm1 = s[-1];
            u32 wm2 = s[-2];
            u32 t1 = prmt5432(wm1, t0);
            u32 t2 = wm1;
            u32 t3 = prmt5432(wm2, wm1);
            u32 t4 = wm2;
            u32 v = hfma2(w42, t0, hfma2(w32, t1, hfma2(w22, t2, hfma2(w12, t3, hfma2(w02, t4, bc2)))));
            if (zh && 2*q < HALO) v = 0u;
            hreg[p] = v;
            sreg[p] = 0u;
            b1[PADW + q] = v;
        }
    }
    nbr_sync(wid);

    u32* cur = b1;
    u32* nxt = b0;

    // ---- layer 0 (d=1): odd offsets via PRMT ----
    {
        const u32 fw0 = duph(ws[8]),   fw1 = duph(ws[9]),   fw2 = duph(ws[10]);
        const u32 fw3 = duph(ws[11]),  fw4 = duph(ws[12]);
        const u32 gw0 = duph(ws[188]), gw1 = duph(ws[189]), gw2 = duph(ws[190]);
        const u32 gw3 = duph(ws[191]), gw4 = duph(ws[192]);
        const u32 fb2 = duph(ws[158]), gb2 = duph(ws[338]);
        const u32 rw2 = duph(ws[368]), negc = duph(ws[398]);
        #pragma unroll
        for (int p = 0; p < NPAIR; p++) {
            int q = bq + 32 * p;
            const u32* s = cur + PADW + q;
            u32 t0  = hreg[p];
            u32 wm1 = s[-1];
            u32 wm2 = s[-2];
            u32 t1 = prmt5432(wm1, t0);
            u32 t2 = wm1;
            u32 t3 = prmt5432(wm2, wm1);
            u32 t4 = wm2;

            u32 fp = hfma2(fw4, t0, hfma2(fw3, t1, hfma2(fw2, t2, hfma2(fw1, t3, hfma2(fw0, t4, fb2)))));
            u32 gp = hfma2(gw4, t0, hfma2(gw3, t1, hfma2(gw2, t2, hfma2(gw1, t3, hfma2(gw0, t4, gb2)))));

            u32 f2v = htanh2(fp);
            u32 g2v = hfma2(htanh2(gp), halfh, halfh);
            u32 z   = hmul2(f2v, g2v);
            sreg[p] = hadd2(sreg[p], z);
            u32 hn  = hfma2(z, rw2, t0);
            if (zh && 2*q < HALO) hn = negc;
            hreg[p] = hn;
            nxt[PADW + q] = hn;
        }
        nbr_sync(wid);
        u32* tmp = cur; cur = nxt; nxt = tmp;
    }

    // ---- layers 1..28: static dilation cycle (2,4,8,6) x 7 ----
    int k = 1;
    #pragma unroll 1
    for (int j = 0; j < 7; j++) {
        layer_even<2, true>(k,   cur, nxt, ws, bq, wid, zh, hreg, sreg, halfh);
        { u32* t = cur; cur = nxt; nxt = t; }
        layer_even<4, true>(k+1, cur, nxt, ws, bq, wid, zh, hreg, sreg, halfh);
        { u32* t = cur; cur = nxt; nxt = t; }
        layer_even<8, true>(k+2, cur, nxt, ws, bq, wid, zh, hreg, sreg, halfh);
        { u32* t = cur; cur = nxt; nxt = t; }
        layer_even<6, true>(k+3, cur, nxt, ws, bq, wid, zh, hreg, sreg, halfh);
        { u32* t = cur; cur = nxt; nxt = t; }
        k += 4;
    }
    // ---- layer 29 (d=2): skips only (no store, no sync) ----
    layer_even<2, false>(29, cur, nxt, ws, bq, wid, zh, hreg, sreg, halfh);

    // ---- epilogue: 1x1 convs + mu-law (f32); v kept packed in vreg ----
    const float c1wv = ws[428], c1bv = ws[429], c2wv = ws[430], c2bv = ws[431];
    u64 vreg[NPAIR];
    float lmax = NEGBIG;
    #pragma unroll
    for (int p = 0; p < NPAIR; p++) {
        int q = bq + 32 * p;
        int i = 2*q;
        int g = g0 + i;
        float v0 = NEGBIG, v1 = NEGBIG;
        if (i >= HALO && g < T_LEN) {
            float2 sv = uph(sreg[p]);
            float r0 = fmaf(fmaxf(sv.x, 0.0f), c1wv, c1bv);
            r0 = fmaf(fmaxf(r0, 0.0f), c2wv, c2bv);
            v0 = copysignf((__expf(fabsf(r0) * LN256) - 1.0f) * (1.0f / 255.0f), r0);
            float r1 = fmaf(fmaxf(sv.y, 0.0f), c1wv, c1bv);
            r1 = fmaf(fmaxf(r1, 0.0f), c2wv, c2bv);
            v1 = copysignf((__expf(fabsf(r1) * LN256) - 1.0f) * (1.0f / 255.0f), r1);
        }
        vreg[p] = pk(v0, v1);
        lmax = fmaxf(lmax, fmaxf(v0, v1));
    }

    // ---- tile max + exp-sum (full-CTA sync resumes here) ----
    __syncthreads();
    float* red = (float*)smem;
    red[tid] = lmax;
    __syncthreads();
    if (tid < 128) red[tid] = fmaxf(fmaxf(red[tid], red[tid + 128]), red[tid + 256]);
    __syncthreads();
    #pragma unroll
    for (int off = 64; off > 0; off >>= 1) {
        if (tid < off) red[tid] = fmaxf(red[tid], red[tid + off]);
        __syncthreads();
    }
    const float tmax = red[0];
    __syncthreads();

    float lsum = 0.0f;
    #pragma unroll
    for (int p = 0; p < NPAIR; p++) {
        float v0, v1;
        upk(vreg[p], v0, v1);
        lsum += __expf(v0 - tmax) + __expf(v1 - tmax);
    }
    red[tid] = lsum;
    __syncthreads();
    if (tid < 128) red[tid] = red[tid] + red[tid + 128] + red[tid + 256];
    __syncthreads();
    #pragma unroll
    for (int off = 64; off > 0; off >>= 1) {
        if (tid < off) red[tid] = red[tid] + red[tid + off];
        __syncthreads();
    }
    if (tid == 0) {
        g_tilemax[b * NTILES + tile] = tmax;
        g_tilesum[b * NTILES + tile] = red[0];
        __threadfence();
    }
    __syncthreads();

    // ---- software grid barrier (all 296 CTAs co-resident) ----
    if (tid == 0) {
        volatile u32* ep = &g_epoch;
        u32 my = *ep;
        u32 t = atomicAdd(&g_arrive, 1u);
        if (t == NCTAS - 1) {
            g_arrive = 0;
            __threadfence();
            atomicAdd(&g_epoch, 1u);
        } else {
            long long guard = 0;
            while (*ep == my && guard < (1LL << 30)) { __nanosleep(64); guard++; }
        }
        __threadfence();
    }
    __syncthreads();

    // ---- combine all tiles of this batch -> bmax, inv; final write ----
    {
        volatile float* vtm = (volatile float*)g_tilemax;
        volatile float* vts = (volatile float*)g_tilesum;
        float m = NEGBIG, s = 0.0f;
        if (tid < NTILES) { m = vtm[b * NTILES + tid]; s = vts[b * NTILES + tid]; }
        if (tid < 64) red[tid] = (tid < NTILES) ? m : NEGBIG;
        __syncthreads();
        #pragma unroll
        for (int off = 32; off > 0; off >>= 1) {
            if (tid < off) red[tid] = fmaxf(red[tid], red[tid + off]);
            __syncthreads();
        }
        float bmax = red[0];
        __syncthreads();
        if (tid < 64) red[tid] = (tid < NTILES) ? s * __expf(m - bmax) : 0.0f;
        __syncthreads();
        #pragma unroll
        for (int off = 32; off > 0; off >>= 1) {
            if (tid < off) red[tid] = red[tid] + red[tid + off];
            __syncthreads();
        }
        float inv = 1.0f / red[0];

        #pragma unroll
        for (int p = 0; p < NPAIR; p++) {
            int q = bq + 32 * p;
            int i = 2*q;
            int g = g0 + i;
            if (i >= HALO && g < T_LEN) {
                float v0, v1;
                upk(vreg[p], v0, v1);
                float e0 = __expf(v0 - bmax) * inv;
                float e1 = __expf(v1 - bmax) * inv;
                *(float2*)(out + base + g) = make_float2(e0, e1);
            }
        }
    }
}

extern "C" void kernel_launch(void* const* d_in, const int* in_sizes, int n_in,
                              void* d_out, int out_size)
{
    const float* x   = (const float*)d_in[0];
    const float* cw  = (const float*)d_in[1];
    const float* cb  = (const float*)d_in[2];
    const float* fw  = (const float*)d_in[3];
    const float* fb  = (const float*)d_in[4];
    const float* gw  = (const float*)d_in[5];
    const float* gb  = (const float*)d_in[6];
    const float* rw  = (const float*)d_in[7];
    const float* rb  = (const float*)d_in[8];
    const float* c1w = (const float*)d_in[9];
    const float* c1b = (const float*)d_in[10];
    const float* c2w = (const float*)d_in[11];
    const float* c2b = (const float*)d_in[12];
    float* out = (float*)d_out;

    cudaFuncSetAttribute(wavenet_k1, cudaFuncAttributeMaxDynamicSharedMemorySize, SMEM_BYTES);

    wavenet_k1<<<dim3(NTILES, BATCH), NTH, SMEM_BYTES>>>(
        x, cw, cb, fw, fb, gw, gb, rw, rb, c1w, c1b, c2w, c2b, out);
}

// round 11
// speedup vs baseline: 1.1144x; 1.0429x over previous
#include <cuda_runtime.h>
#include <cuda_fp16.h>

#define N_LAYERS 30
#define T_LEN    262144
#define BATCH    8
#define NTH      512
#define NPAIR    15
#define LEXT     15360                   // NTH*2*NPAIR
#define HALO     576
#define TILE     (LEXT - HALO)           // 14784
#define NTILES   18                      // 18*14784 = 266112 >= 262144
#define NCTAS    (NTILES * BATCH)        // 144 <= 148 (occ 1, all co-resident)
#define PADL     32
#define PADW     (PADL/2)                // 16 words
#define BUFU32   (PADW + LEXT/2)         // 7696 words per f16x2 buffer
#define WOFFB    (2 * BUFU32 * 4)        // 61568
#define SMEM_BYTES (WOFFB + 448 * 4)     // 63360

#define LN256  5.545177444479562f
#define NEGBIG -3.402823466e38f

typedef unsigned long long u64;
typedef unsigned int u32;

__device__ float g_tilemax[NCTAS];
__device__ float g_tilesum[NCTAS];
__device__ u32   g_arrive;   // zero-init
__device__ u32   g_epoch;    // zero-init

// ---------- f32x2 helpers (epilogue only) ----------
__device__ __forceinline__ u64 pk(float lo, float hi) {
    u64 r; asm("mov.b64 %0,{%1,%2};" : "=l"(r) : "f"(lo), "f"(hi)); return r;
}
__device__ __forceinline__ void upk(u64 v, float& lo, float& hi) {
    asm("mov.b64 {%0,%1},%2;" : "=f"(lo), "=f"(hi) : "l"(v));
}

// ---------- f16x2 helpers ----------
__device__ __forceinline__ u32 hfma2(u32 a, u32 b, u32 c) {
    u32 d; asm("fma.rn.f16x2 %0,%1,%2,%3;" : "=r"(d) : "r"(a), "r"(b), "r"(c)); return d;
}
__device__ __forceinline__ u32 hmul2(u32 a, u32 b) {
    u32 d; asm("mul.rn.f16x2 %0,%1,%2;" : "=r"(d) : "r"(a), "r"(b)); return d;
}
__device__ __forceinline__ u32 hadd2(u32 a, u32 b) {
    u32 d; asm("add.rn.f16x2 %0,%1,%2;" : "=r"(d) : "r"(a), "r"(b)); return d;
}
__device__ __forceinline__ u32 htanh2(u32 a) {
    u32 d; asm("tanh.approx.f16x2 %0,%1;" : "=r"(d) : "r"(a)); return d;
}
__device__ __forceinline__ u32 pkh(float lo, float hi) {
    u32 d; asm("cvt.rn.f16x2.f32 %0,%1,%2;" : "=r"(d) : "f"(hi), "f"(lo)); return d;
}
__device__ __forceinline__ u32 duph(float w) {
    u32 d; asm("cvt.rn.f16x2.f32 %0,%1,%1;" : "=r"(d) : "f"(w)); return d;
}
__device__ __forceinline__ float2 uph(u32 v) {
    __half2 h = *reinterpret_cast<__half2*>(&v);
    return __half22float2(h);
}
__device__ __forceinline__ u32 prmt5432(u32 a, u32 b) {
    u32 d; asm("prmt.b32 %0,%1,%2,0x5432;" : "=r"(d) : "r"(a), "r"(b)); return d;
}

// One gated residual layer, even dilation D, f16x2, bias-folded residual.
template<int D, bool STORE>
__device__ __forceinline__ void layer_even(int k, const u32* cur, u32* nxt,
                                           const float* ws, int tid, bool zh,
                                           u32* hreg, u32* sreg, u32 halfh)
{
    const u32 fw0 = duph(ws[8+5*k]),  fw1 = duph(ws[9+5*k]),  fw2 = duph(ws[10+5*k]);
    const u32 fw3 = duph(ws[11+5*k]), fw4 = duph(ws[12+5*k]);
    const u32 gw0 = duph(ws[188+5*k]), gw1 = duph(ws[189+5*k]), gw2 = duph(ws[190+5*k]);
    const u32 gw3 = duph(ws[191+5*k]), gw4 = duph(ws[192+5*k]);
    const u32 fb2 = duph(ws[158+k]), gb2 = duph(ws[338+k]);
    u32 rw2 = 0, negc = 0;
    if (STORE) { rw2 = duph(ws[368+k]); negc = duph(ws[398+k]); }

    #pragma unroll
    for (int p = 0; p < NPAIR; p++) {
        int q = tid + p * NTH;
        const u32* s = cur + PADW + q;
        u32 t1 = s[-(D/2)];
        u32 t2 = s[-D];
        u32 t3 = s[-(3*D/2)];
        u32 t4 = s[-2*D];
        u32 t0 = hreg[p];

        u32 fp = hfma2(fw4, t0, hfma2(fw3, t1, hfma2(fw2, t2, hfma2(fw1, t3, hfma2(fw0, t4, fb2)))));
        u32 gp = hfma2(gw4, t0, hfma2(gw3, t1, hfma2(gw2, t2, hfma2(gw1, t3, hfma2(gw0, t4, gb2)))));

        u32 f2v = htanh2(fp);
        u32 g2v = hfma2(htanh2(gp), halfh, halfh);   // sigmoid (gate pre-scaled 0.5)
        u32 z   = hmul2(f2v, g2v);
        sreg[p] = hadd2(sreg[p], z);
        if (STORE) {
            u32 hn = hfma2(z, rw2, t0);              // rb folded into next biases
            if (zh && 2*q < HALO) hn = negc;         // H = -C_{k+1} in zero-pad halo
            hreg[p] = hn;
            nxt[PADW + q] = hn;
        }
    }
    if (STORE) __syncthreads();
}

__global__ __launch_bounds__(NTH, 1)
void wavenet_k1(const float* __restrict__ x,
                const float* __restrict__ cw,  const float* __restrict__ cb,
                const float* __restrict__ fw,  const float* __restrict__ fb,
                const float* __restrict__ gw,  const float* __restrict__ gb,
                const float* __restrict__ rw,  const float* __restrict__ rb,
                const float* __restrict__ c1w, const float* __restrict__ c1b,
                const float* __restrict__ c2w, const float* __restrict__ c2b,
                float* __restrict__ out)
{
    extern __shared__ char smem[];
    u32*   b0 = (u32*)smem;
    u32*   b1 = b0 + BUFU32;
    float* ws = (float*)(smem + WOFFB);

    const int tid  = threadIdx.x;
    const int tile = blockIdx.x;
    const int b    = blockIdx.y;
    const long long base = (long long)b * T_LEN;
    const int g0 = tile * TILE - HALO;
    const bool zh = (tile == 0);

    // ---- weights -> smem (gate pre-scaled by 0.5) ----
    if (tid < 5)  ws[tid] = cw[tid];
    if (tid == 5) ws[5]   = cb[0];
    for (int j = tid; j < 150; j += NTH) { ws[8 + j] = fw[j]; ws[188 + j] = gw[j] * 0.5f; }
    for (int j = tid; j < 30;  j += NTH) {
        ws[158 + j] = fb[j]; ws[338 + j] = gb[j] * 0.5f;
        ws[368 + j] = rw[j]; ws[398 + j] = rb[j];
    }
    if (tid == 0) { ws[428] = c1w[0]; ws[429] = c1b[0]; ws[430] = c2w[0]; ws[431] = c2b[0]; }
    if (tid < PADW) { b0[tid] = 0u; b1[tid] = 0u; }
    __syncthreads();

    // ---- thread 0: fold cumulative residual bias C into conv biases ----
    // H_k = h_k - C_k, C_{k+1} = C_k + rb_k; taps share C -> fb' = fb + C*sum(fw)
    if (tid == 0) {
        float C = 0.0f;
        for (int k = 0; k < N_LAYERS; k++) {
            float sf = ws[8+5*k] + ws[9+5*k] + ws[10+5*k] + ws[11+5*k] + ws[12+5*k];
            float sg = ws[188+5*k] + ws[189+5*k] + ws[190+5*k] + ws[191+5*k] + ws[192+5*k];
            ws[158+k] += C * sf;
            ws[338+k] += C * sg;     // gate side already carries the 0.5 scale
            C += ws[398+k];          // raw rb_k
            ws[398+k] = -C;          // -C_{k+1} (halo forcing constant)
        }
    }

    // ---- stage x -> f16x2 buf0 ----
    #pragma unroll
    for (int p = 0; p < NPAIR; p++) {
        int q = tid + p * NTH;
        int g = g0 + 2*q;
        float2 v;
        if (g >= 0 && g + 1 < T_LEN) {
            v = *(const float2*)(x + base + g);
        } else {
            v.x = (g     >= 0 && g     < T_LEN) ? x[base + g]     : 0.0f;
            v.y = (g + 1 >= 0 && g + 1 < T_LEN) ? x[base + g + 1] : 0.0f;
        }
        b0[PADW + q] = pkh(v.x, v.y);
    }
    __syncthreads();   // covers staging + bias fold

    const u32 halfh = duph(0.5f);
    u32 hreg[NPAIR];
    u32 sreg[NPAIR];

    // ---- causal conv (d=1): b0 -> b1 + hreg (C_0 = 0) ----
    {
        const u32 w02 = duph(ws[0]), w12 = duph(ws[1]), w22 = duph(ws[2]),
                  w32 = duph(ws[3]), w42 = duph(ws[4]), bc2 = duph(ws[5]);
        #pragma unroll
        for (int p = 0; p < NPAIR; p++) {
            int q = tid + p * NTH;
            const u32* s = b0 + PADW + q;
            u32 t0  = s[0];
            u32 wm1 = s[-1];
            u32 wm2 = s[-2];
            u32 t1 = prmt5432(wm1, t0);
            u32 t2 = wm1;
            u32 t3 = prmt5432(wm2, wm1);
            u32 t4 = wm2;
            u32 v = hfma2(w42, t0, hfma2(w32, t1, hfma2(w22, t2, hfma2(w12, t3, hfma2(w02, t4, bc2)))));
            if (zh && 2*q < HALO) v = 0u;
            hreg[p] = v;
            sreg[p] = 0u;
            b1[PADW + q] = v;
        }
    }
    __syncthreads();

    u32* cur = b1;
    u32* nxt = b0;

    // ---- layer 0 (d=1): odd offsets via PRMT ----
    {
        const u32 fw0 = duph(ws[8]),   fw1 = duph(ws[9]),   fw2 = duph(ws[10]);
        const u32 fw3 = duph(ws[11]),  fw4 = duph(ws[12]);
        const u32 gw0 = duph(ws[188]), gw1 = duph(ws[189]), gw2 = duph(ws[190]);
        const u32 gw3 = duph(ws[191]), gw4 = duph(ws[192]);
        const u32 fb2 = duph(ws[158]), gb2 = duph(ws[338]);
        const u32 rw2 = duph(ws[368]), negc = duph(ws[398]);
        #pragma unroll
        for (int p = 0; p < NPAIR; p++) {
            int q = tid + p * NTH;
            const u32* s = cur + PADW + q;
            u32 t0  = hreg[p];
            u32 wm1 = s[-1];
            u32 wm2 = s[-2];
            u32 t1 = prmt5432(wm1, t0);
            u32 t2 = wm1;
            u32 t3 = prmt5432(wm2, wm1);
            u32 t4 = wm2;

            u32 fp = hfma2(fw4, t0, hfma2(fw3, t1, hfma2(fw2, t2, hfma2(fw1, t3, hfma2(fw0, t4, fb2)))));
            u32 gp = hfma2(gw4, t0, hfma2(gw3, t1, hfma2(gw2, t2, hfma2(gw1, t3, hfma2(gw0, t4, gb2)))));

            u32 f2v = htanh2(fp);
            u32 g2v = hfma2(htanh2(gp), halfh, halfh);
            u32 z   = hmul2(f2v, g2v);
            sreg[p] = hadd2(sreg[p], z);
            u32 hn  = hfma2(z, rw2, t0);
            if (zh && 2*q < HALO) hn = negc;
            hreg[p] = hn;
            nxt[PADW + q] = hn;
        }
        __syncthreads();
        u32* tmp = cur; cur = nxt; nxt = tmp;
    }

    // ---- layers 1..28: static dilation cycle (2,4,8,6) x 7 ----
    int k = 1;
    #pragma unroll 1
    for (int j = 0; j < 7; j++) {
        layer_even<2, true>(k,   cur, nxt, ws, tid, zh, hreg, sreg, halfh);
        { u32* t = cur; cur = nxt; nxt = t; }
        layer_even<4, true>(k+1, cur, nxt, ws, tid, zh, hreg, sreg, halfh);
        { u32* t = cur; cur = nxt; nxt = t; }
        layer_even<8, true>(k+2, cur, nxt, ws, tid, zh, hreg, sreg, halfh);
        { u32* t = cur; cur = nxt; nxt = t; }
        layer_even<6, true>(k+3, cur, nxt, ws, tid, zh, hreg, sreg, halfh);
        { u32* t = cur; cur = nxt; nxt = t; }
        k += 4;
    }
    // ---- layer 29 (d=2): skips only ----
    layer_even<2, false>(29, cur, nxt, ws, tid, zh, hreg, sreg, halfh);

    // ---- epilogue: 1x1 convs + mu-law (f32); v kept packed in vreg ----
    const float c1wv = ws[428], c1bv = ws[429], c2wv = ws[430], c2bv = ws[431];
    u64 vreg[NPAIR];
    float lmax = NEGBIG;
    #pragma unroll
    for (int p = 0; p < NPAIR; p++) {
        int q = tid + p * NTH;
        int i = 2*q;
        int g = g0 + i;
        float v0 = NEGBIG, v1 = NEGBIG;
        if (i >= HALO && g < T_LEN) {
            float2 sv = uph(sreg[p]);
            float r0 = fmaf(fmaxf(sv.x, 0.0f), c1wv, c1bv);
            r0 = fmaf(fmaxf(r0, 0.0f), c2wv, c2bv);
            v0 = copysignf((__expf(fabsf(r0) * LN256) - 1.0f) * (1.0f / 255.0f), r0);
            float r1 = fmaf(fmaxf(sv.y, 0.0f), c1wv, c1bv);
            r1 = fmaf(fmaxf(r1, 0.0f), c2wv, c2bv);
            v1 = copysignf((__expf(fabsf(r1) * LN256) - 1.0f) * (1.0f / 255.0f), r1);
        }
        vreg[p] = pk(v0, v1);
        lmax = fmaxf(lmax, fmaxf(v0, v1));
    }

    // ---- tile max + exp-sum (reuse smem as fp32 scratch) ----
    __syncthreads();
    float* red = (float*)smem;
    red[tid] = lmax;
    __syncthreads();
    #pragma unroll
    for (int off = 256; off > 0; off >>= 1) {
        if (tid < off) red[tid] = fmaxf(red[tid], red[tid + off]);
        __syncthreads();
    }
    const float tmax = red[0];
    __syncthreads();

    float lsum = 0.0f;
    #pragma unroll
    for (int p = 0; p < NPAIR; p++) {
        float v0, v1;
        upk(vreg[p], v0, v1);
        lsum += __expf(v0 - tmax) + __expf(v1 - tmax);
    }
    red[tid] = lsum;
    __syncthreads();
    #pragma unroll
    for (int off = 256; off > 0; off >>= 1) {
        if (tid < off) red[tid] = red[tid] + red[tid + off];
        __syncthreads();
    }
    if (tid == 0) {
        g_tilemax[b * NTILES + tile] = tmax;
        g_tilesum[b * NTILES + tile] = red[0];
        __threadfence();
    }
    __syncthreads();

    // ---- software grid barrier (144 CTAs co-resident at occ 1) ----
    if (tid == 0) {
        volatile u32* ep = &g_epoch;
        u32 my = *ep;
        u32 t = atomicAdd(&g_arrive, 1u);
        if (t == NCTAS - 1) {
            g_arrive = 0;
            __threadfence();
            atomicAdd(&g_epoch, 1u);
        } else {
            long long guard = 0;
            while (*ep == my && guard < (1LL << 30)) { __nanosleep(64); guard++; }
        }
        __threadfence();
    }
    __syncthreads();

    // ---- combine all tiles of this batch -> bmax, inv; final write ----
    {
        volatile float* vtm = (volatile float*)g_tilemax;
        volatile float* vts = (volatile float*)g_tilesum;
        float m = NEGBIG, s = 0.0f;
        if (tid < NTILES) { m = vtm[b * NTILES + tid]; s = vts[b * NTILES + tid]; }
        if (tid < 32) red[tid] = (tid < NTILES) ? m : NEGBIG;
        __syncthreads();
        #pragma unroll
        for (int off = 16; off > 0; off >>= 1) {
            if (tid < off) red[tid] = fmaxf(red[tid], red[tid + off]);
            __syncthreads();
        }
        float bmax = red[0];
        __syncthreads();
        if (tid < 32) red[tid] = (tid < NTILES) ? s * __expf(m - bmax) : 0.0f;
        __syncthreads();
        #pragma unroll
        for (int off = 16; off > 0; off >>= 1) {
            if (tid < off) red[tid] = red[tid] + red[tid + off];
            __syncthreads();
        }
        float inv = 1.0f / red[0];

        #pragma unroll
        for (int p = 0; p < NPAIR; p++) {
            int q = tid + p * NTH;
            int i = 2*q;
            int g = g0 + i;
            if (i >= HALO && g < T_LEN) {
                float v0, v1;
                upk(vreg[p], v0, v1);
                float e0 = __expf(v0 - bmax) * inv;
                float e1 = __expf(v1 - bmax) * inv;
                *(float2*)(out + base + g) = make_float2(e0, e1);
            }
        }
    }
}

extern "C" void kernel_launch(void* const* d_in, const int* in_sizes, int n_in,
                              void* d_out, int out_size)
{
    const float* x   = (const float*)d_in[0];
    const float* cw  = (const float*)d_in[1];
    const float* cb  = (const float*)d_in[2];
    const float* fw  = (const float*)d_in[3];
    const float* fb  = (const float*)d_in[4];
    const float* gw  = (const float*)d_in[5];
    const float* gb  = (const float*)d_in[6];
    const float* rw  = (const float*)d_in[7];
    const float* rb  = (const float*)d_in[8];
    const float* c1w = (const float*)d_in[9];
    const float* c1b = (const float*)d_in[10];
    const float* c2w = (const float*)d_in[11];
    const float* c2b = (const float*)d_in[12];
    float* out = (float*)d_out;

    cudaFuncSetAttribute(wavenet_k1, cudaFuncAttributeMaxDynamicSharedMemorySize, SMEM_BYTES);

    wavenet_k1<<<dim3(NTILES, BATCH), NTH, SMEM_BYTES>>>(
        x, cw, cb, fw, fb, gw, gb, rw, rb, c1w, c1b, c2w, c2b, out);
}

// round 12
// speedup vs baseline: 1.1585x; 1.0396x over previous
#include <cuda_runtime.h>
#include <cuda_fp16.h>

#define N_LAYERS 30
#define T_LEN    262144
#define BATCH    8
#define NTH      256
#define NPAIR    15
#define LEXT     7680                    // NTH*2*NPAIR
#define HALO     576
#define TILE     (LEXT - HALO)           // 7104
#define NTILES   37
#define NCTAS    (NTILES * BATCH)        // 296 = 148 SMs x occ 2
#define PADL     32
#define PADW     (PADL/2)                // 16 words
#define BUFU32   (PADW + LEXT/2)         // 3856 words per f16x2 buffer
#define WOFFB    (2 * BUFU32 * 4)        // 30848
#define SMEM_BYTES (WOFFB + 448 * 4)     // 32640

#define LN256  5.545177444479562f
#define NEGBIG -3.402823466e38f

typedef unsigned long long u64;
typedef unsigned int u32;

__device__ float g_tilemax[NCTAS];
__device__ float g_tilesum[NCTAS];
__device__ u32   g_arrive;   // zero-init
__device__ u32   g_epoch;    // zero-init

// ---------- f32x2 helpers (epilogue only) ----------
__device__ __forceinline__ u64 pk(float lo, float hi) {
    u64 r; asm("mov.b64 %0,{%1,%2};" : "=l"(r) : "f"(lo), "f"(hi)); return r;
}
__device__ __forceinline__ void upk(u64 v, float& lo, float& hi) {
    asm("mov.b64 {%0,%1},%2;" : "=f"(lo), "=f"(hi) : "l"(v));
}

// ---------- f16x2 helpers ----------
__device__ __forceinline__ u32 hfma2(u32 a, u32 b, u32 c) {
    u32 d; asm("fma.rn.f16x2 %0,%1,%2,%3;" : "=r"(d) : "r"(a), "r"(b), "r"(c)); return d;
}
__device__ __forceinline__ u32 hmul2(u32 a, u32 b) {
    u32 d; asm("mul.rn.f16x2 %0,%1,%2;" : "=r"(d) : "r"(a), "r"(b)); return d;
}
__device__ __forceinline__ u32 hadd2(u32 a, u32 b) {
    u32 d; asm("add.rn.f16x2 %0,%1,%2;" : "=r"(d) : "r"(a), "r"(b)); return d;
}
__device__ __forceinline__ u32 htanh2(u32 a) {
    u32 d; asm("tanh.approx.f16x2 %0,%1;" : "=r"(d) : "r"(a)); return d;
}
__device__ __forceinline__ u32 pkh(float lo, float hi) {
    u32 d; asm("cvt.rn.f16x2.f32 %0,%1,%2;" : "=r"(d) : "f"(hi), "f"(lo)); return d;
}
__device__ __forceinline__ u32 duph(float w) {
    u32 d; asm("cvt.rn.f16x2.f32 %0,%1,%1;" : "=r"(d) : "f"(w)); return d;
}
__device__ __forceinline__ float2 uph(u32 v) {
    __half2 h = *reinterpret_cast<__half2*>(&v);
    return __half22float2(h);
}
__device__ __forceinline__ u32 prmt5432(u32 a, u32 b) {
    u32 d; asm("prmt.b32 %0,%1,%2,0x5432;" : "=r"(d) : "r"(a), "r"(b)); return d;
}

// One gated residual layer, even dilation D, f16x2, bias-folded residual.
template<int D, bool STORE>
__device__ __forceinline__ void layer_even(int k, const u32* cur, u32* nxt,
                                           const float* ws, int tid, bool zh,
                                           u32* hreg, u32* sreg, u32 halfh)
{
    const u32 fw0 = duph(ws[8+5*k]),  fw1 = duph(ws[9+5*k]),  fw2 = duph(ws[10+5*k]);
    const u32 fw3 = duph(ws[11+5*k]), fw4 = duph(ws[12+5*k]);
    const u32 gw0 = duph(ws[188+5*k]), gw1 = duph(ws[189+5*k]), gw2 = duph(ws[190+5*k]);
    const u32 gw3 = duph(ws[191+5*k]), gw4 = duph(ws[192+5*k]);
    const u32 fb2 = duph(ws[158+k]), gb2 = duph(ws[338+k]);
    u32 rw2 = 0, negc = 0;
    if (STORE) { rw2 = duph(ws[368+k]); negc = duph(ws[398+k]); }

    #pragma unroll
    for (int p = 0; p < NPAIR; p++) {
        int q = tid + p * NTH;
        const u32* s = cur + PADW + q;
        u32 t1 = s[-(D/2)];
        u32 t2 = s[-D];
        u32 t3 = s[-(3*D/2)];
        u32 t4 = s[-2*D];
        u32 t0 = hreg[p];

        u32 fp = hfma2(fw4, t0, hfma2(fw3, t1, hfma2(fw2, t2, hfma2(fw1, t3, hfma2(fw0, t4, fb2)))));
        u32 gp = hfma2(gw4, t0, hfma2(gw3, t1, hfma2(gw2, t2, hfma2(gw1, t3, hfma2(gw0, t4, gb2)))));

        u32 f2v = htanh2(fp);
        u32 g2v = hfma2(htanh2(gp), halfh, halfh);   // sigmoid (gate pre-scaled 0.5)
        u32 z   = hmul2(f2v, g2v);
        sreg[p] = hadd2(sreg[p], z);
        if (STORE) {
            u32 hn = hfma2(z, rw2, t0);              // rb folded into next biases
            if (zh && 2*q < HALO) hn = negc;         // H = -C_{k+1} in zero-pad halo
            hreg[p] = hn;
            nxt[PADW + q] = hn;
        }
    }
    if (STORE) __syncthreads();
}

__global__ __launch_bounds__(NTH, 2)
void wavenet_k1(const float* __restrict__ x,
                const float* __restrict__ cw,  const float* __restrict__ cb,
                const float* __restrict__ fw,  const float* __restrict__ fb,
                const float* __restrict__ gw,  const float* __restrict__ gb,
                const float* __restrict__ rw,  const float* __restrict__ rb,
                const float* __restrict__ c1w, const float* __restrict__ c1b,
                const float* __restrict__ c2w, const float* __restrict__ c2b,
                float* __restrict__ out)
{
    extern __shared__ char smem[];
    u32*   b0 = (u32*)smem;
    u32*   b1 = b0 + BUFU32;
    float* ws = (float*)(smem + WOFFB);

    const int tid  = threadIdx.x;
    const int tile = blockIdx.x;
    const int b    = blockIdx.y;
    const long long base = (long long)b * T_LEN;
    const int g0 = tile * TILE - HALO;
    const bool zh = (tile == 0);

    // ---- weights -> smem (gate pre-scaled by 0.5) ----
    if (tid < 5)  ws[tid] = cw[tid];
    if (tid == 5) ws[5]   = cb[0];
    for (int j = tid; j < 150; j += NTH) { ws[8 + j] = fw[j]; ws[188 + j] = gw[j] * 0.5f; }
    for (int j = tid; j < 30;  j += NTH) {
        ws[158 + j] = fb[j]; ws[338 + j] = gb[j] * 0.5f;
        ws[368 + j] = rw[j]; ws[398 + j] = rb[j];
    }
    if (tid == 0) { ws[428] = c1w[0]; ws[429] = c1b[0]; ws[430] = c2w[0]; ws[431] = c2b[0]; }
    if (tid < PADW) { b0[tid] = 0u; b1[tid] = 0u; }
    __syncthreads();

    // ---- thread 0: fold cumulative residual bias C into conv biases ----
    // H_k = h_k - C_k, C_{k+1} = C_k + rb_k; taps share C -> fb' = fb + C*sum(fw)
    if (tid == 0) {
        float C = 0.0f;
        for (int k = 0; k < N_LAYERS; k++) {
            float sf = ws[8+5*k] + ws[9+5*k] + ws[10+5*k] + ws[11+5*k] + ws[12+5*k];
            float sg = ws[188+5*k] + ws[189+5*k] + ws[190+5*k] + ws[191+5*k] + ws[192+5*k];
            ws[158+k] += C * sf;
            ws[338+k] += C * sg;     // gate side already carries the 0.5 scale
            C += ws[398+k];          // raw rb_k
            ws[398+k] = -C;          // -C_{k+1} (halo forcing constant)
        }
    }

    // ---- stage x -> f16x2 buf0 ----
    #pragma unroll
    for (int p = 0; p < NPAIR; p++) {
        int q = tid + p * NTH;
        int g = g0 + 2*q;
        float2 v;
        if (g >= 0 && g + 1 < T_LEN) {
            v = *(const float2*)(x + base + g);
        } else {
            v.x = (g     >= 0 && g     < T_LEN) ? x[base + g]     : 0.0f;
            v.y = (g + 1 >= 0 && g + 1 < T_LEN) ? x[base + g + 1] : 0.0f;
        }
        b0[PADW + q] = pkh(v.x, v.y);
    }
    __syncthreads();   // covers staging + bias fold

    const u32 halfh = duph(0.5f);
    u32 hreg[NPAIR];
    u32 sreg[NPAIR];

    // ---- causal conv (d=1): b0 -> b1 + hreg (C_0 = 0) ----
    {
        const u32 w02 = duph(ws[0]), w12 = duph(ws[1]), w22 = duph(ws[2]),
                  w32 = duph(ws[3]), w42 = duph(ws[4]), bc2 = duph(ws[5]);
        #pragma unroll
        for (int p = 0; p < NPAIR; p++) {
            int q = tid + p * NTH;
            const u32* s = b0 + PADW + q;
            u32 t0  = s[0];
            u32 wm1 = s[-1];
            u32 wm2 = s[-2];
            u32 t1 = prmt5432(wm1, t0);
            u32 t2 = wm1;
            u32 t3 = prmt5432(wm2, wm1);
            u32 t4 = wm2;
            u32 v = hfma2(w42, t0, hfma2(w32, t1, hfma2(w22, t2, hfma2(w12, t3, hfma2(w02, t4, bc2)))));
            if (zh && 2*q < HALO) v = 0u;
            hreg[p] = v;
            sreg[p] = 0u;
            b1[PADW + q] = v;
        }
    }
    __syncthreads();

    u32* cur = b1;
    u32* nxt = b0;

    // ---- layer 0 (d=1): odd offsets via PRMT ----
    {
        const u32 fw0 = duph(ws[8]),   fw1 = duph(ws[9]),   fw2 = duph(ws[10]);
        const u32 fw3 = duph(ws[11]),  fw4 = duph(ws[12]);
        const u32 gw0 = duph(ws[188]), gw1 = duph(ws[189]), gw2 = duph(ws[190]);
        const u32 gw3 = duph(ws[191]), gw4 = duph(ws[192]);
        const u32 fb2 = duph(ws[158]), gb2 = duph(ws[338]);
        const u32 rw2 = duph(ws[368]), negc = duph(ws[398]);
        #pragma unroll
        for (int p = 0; p < NPAIR; p++) {
            int q = tid + p * NTH;
            const u32* s = cur + PADW + q;
            u32 t0  = hreg[p];
            u32 wm1 = s[-1];
            u32 wm2 = s[-2];
            u32 t1 = prmt5432(wm1, t0);
            u32 t2 = wm1;
            u32 t3 = prmt5432(wm2, wm1);
            u32 t4 = wm2;

            u32 fp = hfma2(fw4, t0, hfma2(fw3, t1, hfma2(fw2, t2, hfma2(fw1, t3, hfma2(fw0, t4, fb2)))));
            u32 gp = hfma2(gw4, t0, hfma2(gw3, t1, hfma2(gw2, t2, hfma2(gw1, t3, hfma2(gw0, t4, gb2)))));

            u32 f2v = htanh2(fp);
            u32 g2v = hfma2(htanh2(gp), halfh, halfh);
            u32 z   = hmul2(f2v, g2v);
            sreg[p] = hadd2(sreg[p], z);
            u32 hn  = hfma2(z, rw2, t0);
            if (zh && 2*q < HALO) hn = negc;
            hreg[p] = hn;
            nxt[PADW + q] = hn;
        }
        __syncthreads();
        u32* tmp = cur; cur = nxt; nxt = tmp;
    }

    // ---- layers 1..28: static dilation cycle (2,4,8,6) x 7 ----
    int k = 1;
    #pragma unroll 1
    for (int j = 0; j < 7; j++) {
        layer_even<2, true>(k,   cur, nxt, ws, tid, zh, hreg, sreg, halfh);
        { u32* t = cur; cur = nxt; nxt = t; }
        layer_even<4, true>(k+1, cur, nxt, ws, tid, zh, hreg, sreg, halfh);
        { u32* t = cur; cur = nxt; nxt = t; }
        layer_even<8, true>(k+2, cur, nxt, ws, tid, zh, hreg, sreg, halfh);
        { u32* t = cur; cur = nxt; nxt = t; }
        layer_even<6, true>(k+3, cur, nxt, ws, tid, zh, hreg, sreg, halfh);
        { u32* t = cur; cur = nxt; nxt = t; }
        k += 4;
    }
    // ---- layer 29 (d=2): skips only ----
    layer_even<2, false>(29, cur, nxt, ws, tid, zh, hreg, sreg, halfh);

    // ---- epilogue: 1x1 convs + mu-law (f32); v kept packed in vreg ----
    const float c1wv = ws[428], c1bv = ws[429], c2wv = ws[430], c2bv = ws[431];
    u64 vreg[NPAIR];
    float lmax = NEGBIG;
    #pragma unroll
    for (int p = 0; p < NPAIR; p++) {
        int q = tid + p * NTH;
        int i = 2*q;
        int g = g0 + i;
        float v0 = NEGBIG, v1 = NEGBIG;
        if (i >= HALO && g < T_LEN) {
            float2 sv = uph(sreg[p]);
            float r0 = fmaf(fmaxf(sv.x, 0.0f), c1wv, c1bv);
            r0 = fmaf(fmaxf(r0, 0.0f), c2wv, c2bv);
            v0 = copysignf((__expf(fabsf(r0) * LN256) - 1.0f) * (1.0f / 255.0f), r0);
            float r1 = fmaf(fmaxf(sv.y, 0.0f), c1wv, c1bv);
            r1 = fmaf(fmaxf(r1, 0.0f), c2wv, c2bv);
            v1 = copysignf((__expf(fabsf(r1) * LN256) - 1.0f) * (1.0f / 255.0f), r1);
        }
        vreg[p] = pk(v0, v1);
        lmax = fmaxf(lmax, fmaxf(v0, v1));
    }

    // ---- tile max + exp-sum (reuse smem as fp32 scratch) ----
    __syncthreads();
    float* red = (float*)smem;
    red[tid] = lmax;
    __syncthreads();
    #pragma unroll
    for (int off = 128; off > 0; off >>= 1) {
        if (tid < off) red[tid] = fmaxf(red[tid], red[tid + off]);
        __syncthreads();
    }
    const float tmax = red[0];
    __syncthreads();

    float lsum = 0.0f;
    #pragma unroll
    for (int p = 0; p < NPAIR; p++) {
        float v0, v1;
        upk(vreg[p], v0, v1);
        lsum += __expf(v0 - tmax) + __expf(v1 - tmax);
    }
    red[tid] = lsum;
    __syncthreads();
    #pragma unroll
    for (int off = 128; off > 0; off >>= 1) {
        if (tid < off) red[tid] = red[tid] + red[tid + off];
        __syncthreads();
    }
    if (tid == 0) {
        g_tilemax[b * NTILES + tile] = tmax;
        g_tilesum[b * NTILES + tile] = red[0];
        __threadfence();
    }
    __syncthreads();

    // ---- software grid barrier (296 CTAs co-resident at occ 2) ----
    if (tid == 0) {
        volatile u32* ep = &g_epoch;
        u32 my = *ep;
        u32 t = atomicAdd(&g_arrive, 1u);
        if (t == NCTAS - 1) {
            g_arrive = 0;
            __threadfence();
            atomicAdd(&g_epoch, 1u);
        } else {
            long long guard = 0;
            while (*ep == my && guard < (1LL << 30)) { __nanosleep(64); guard++; }
        }
        __threadfence();
    }
    __syncthreads();

    // ---- combine all tiles of this batch -> bmax, inv; final write ----
    {
        volatile float* vtm = (volatile float*)g_tilemax;
        volatile float* vts = (volatile float*)g_tilesum;
        float m = NEGBIG, s = 0.0f;
        if (tid < NTILES) { m = vtm[b * NTILES + tid]; s = vts[b * NTILES + tid]; }
        if (tid < 64) red[tid] = (tid < NTILES) ? m : NEGBIG;
        __syncthreads();
        #pragma unroll
        for (int off = 32; off > 0; off >>= 1) {
            if (tid < off) red[tid] = fmaxf(red[tid], red[tid + off]);
            __syncthreads();
        }
        float bmax = red[0];
        __syncthreads();
        if (tid < 64) red[tid] = (tid < NTILES) ? s * __expf(m - bmax) : 0.0f;
        __syncthreads();
        #pragma unroll
        for (int off = 32; off > 0; off >>= 1) {
            if (tid < off) red[tid] = red[tid] + red[tid + off];
            __syncthreads();
        }
        float inv = 1.0f / red[0];

        #pragma unroll
        for (int p = 0; p < NPAIR; p++) {
            int q = tid + p * NTH;
            int i = 2*q;
            int g = g0 + i;
            if (i >= HALO && g < T_LEN) {
                float v0, v1;
                upk(vreg[p], v0, v1);
                float e0 = __expf(v0 - bmax) * inv;
                float e1 = __expf(v1 - bmax) * inv;
                *(float2*)(out + base + g) = make_float2(e0, e1);
            }
        }
    }
}

extern "C" void kernel_launch(void* const* d_in, const int* in_sizes, int n_in,
                              void* d_out, int out_size)
{
    const float* x   = (const float*)d_in[0];
    const float* cw  = (const float*)d_in[1];
    const float* cb  = (const float*)d_in[2];
    const float* fw  = (const float*)d_in[3];
    const float* fb  = (const float*)d_in[4];
    const float* gw  = (const float*)d_in[5];
    const float* gb  = (const float*)d_in[6];
    const float* rw  = (const float*)d_in[7];
    const float* rb  = (const float*)d_in[8];
    const float* c1w = (const float*)d_in[9];
    const float* c1b = (const float*)d_in[10];
    const float* c2w = (const float*)d_in[11];
    const float* c2b = (const float*)d_in[12];
    float* out = (float*)d_out;

    cudaFuncSetAttribute(wavenet_k1, cudaFuncAttributeMaxDynamicSharedMemorySize, SMEM_BYTES);

    wavenet_k1<<<dim3(NTILES, BATCH), NTH, SMEM_BYTES>>>(
        x, cw, cb, fw, fb, gw, gb, rw, rb, c1w, c1b, c2w, c2b, out);
}